// round 4
// baseline (speedup 1.0000x reference)
#include <cuda_runtime.h>

#define THREADS 128
#define EPSF 1e-12f

typedef unsigned long long ull;

// ---- f32x2 packed helpers (sm_103a) ----
__device__ __forceinline__ ull pack2(float lo, float hi) {
    ull r; asm("mov.b64 %0, {%1, %2};" : "=l"(r) : "f"(lo), "f"(hi)); return r;
}
__device__ __forceinline__ void unpack2(ull p, float& lo, float& hi) {
    asm("mov.b64 {%0, %1}, %2;" : "=f"(lo), "=f"(hi) : "l"(p));
}
__device__ __forceinline__ ull fma2(ull a, ull b, ull c) {
    ull d; asm("fma.rn.f32x2 %0, %1, %2, %3;" : "=l"(d) : "l"(a), "l"(b), "l"(c)); return d;
}
__device__ __forceinline__ ull add2(ull a, ull b) {
    ull d; asm("add.rn.f32x2 %0, %1, %2;" : "=l"(d) : "l"(a), "l"(b)); return d;
}
__device__ __forceinline__ ull mul2(ull a, ull b) {
    ull d; asm("mul.rn.f32x2 %0, %1, %2;" : "=l"(d) : "l"(a), "l"(b)); return d;
}
__device__ __forceinline__ float frcp(float x) {
    float y; asm("rcp.approx.f32 %0, %1;" : "=f"(y) : "f"(x)); return y;
}

// ---- weights live in the constant bank (uniform datapath, off L1tex) ----
struct CParams {
    ulonglong2 W1p[64 * 3];   // [j][t]: (w,w)-duplicated pairs of transposed W1
    ulonglong2 W2p[64 * 8];   // raw W2 rows, 32 floats = 8 x (2+2)
    ulonglong2 W3p[32 * 4];   // raw W3 rows
    ulonglong2 W4p[16 * 3];   // W4 rows padded 9 -> 12
    ull        b1p[64];       // (b,b) duplicated
    ulonglong2 b2p[8];
    ulonglong2 b3p[4];
    ulonglong2 b4p[3];        // padded 9 -> 12
};
__constant__ CParams cpar;
__device__   CParams g_stage;

__global__ void prep_kernel(
    const float* __restrict__ W1, const float* __restrict__ b1,
    const float* __restrict__ W2, const float* __restrict__ b2,
    const float* __restrict__ W3, const float* __restrict__ b3,
    const float* __restrict__ W4, const float* __restrict__ b4)
{
    int t = threadIdx.x;
    // W1 transposed + duplicated: pair t of output j holds inputs (2t, 2t+1)
    for (int i = t; i < 64 * 3; i += blockDim.x) {
        int j = i / 3, p = i % 3;
        float wa = W1[(2 * p + 0) * 64 + j];
        float wb = W1[(2 * p + 1) * 64 + j];
        g_stage.W1p[i].x = pack2(wa, wa);
        g_stage.W1p[i].y = pack2(wb, wb);
    }
    for (int i = t; i < 64; i += blockDim.x) { float b = b1[i]; g_stage.b1p[i] = pack2(b, b); }
    // W2/W3: raw bit-copies (consecutive output floats are already the lane pairs)
    for (int i = t; i < 64 * 8; i += blockDim.x)
        g_stage.W2p[i] = reinterpret_cast<const ulonglong2*>(W2)[i];
    for (int i = t; i < 8; i += blockDim.x)
        g_stage.b2p[i] = reinterpret_cast<const ulonglong2*>(b2)[i];
    for (int i = t; i < 32 * 4; i += blockDim.x)
        g_stage.W3p[i] = reinterpret_cast<const ulonglong2*>(W3)[i];
    for (int i = t; i < 4; i += blockDim.x)
        g_stage.b3p[i] = reinterpret_cast<const ulonglong2*>(b3)[i];
    // W4 / b4 padded to 12 floats per row
    for (int i = t; i < 16 * 12; i += blockDim.x) {
        int r = i / 12, c = i % 12;
        float v = (c < 9) ? W4[r * 9 + c] : 0.0f;
        reinterpret_cast<float*>(g_stage.W4p)[i] = v;
    }
    for (int i = t; i < 12; i += blockDim.x)
        reinterpret_cast<float*>(g_stage.b4p)[i] = (i < 9) ? b4[i] : 0.0f;
}

// ---- packed-over-two-rows head math + Sinkhorn + store ----
__device__ __forceinline__ void head2(
    const float* __restrict__ xA, const float* __restrict__ xB,
    const float* __restrict__ pA, const float* __restrict__ pB,
    float* __restrict__ out_mus, float* __restrict__ out_V,
    int rowA, int rowB)
{
    // scalar transcendentals per row, then pack over (rowA,rowB)
    ull A00 = pack2(__expf(pA[0]), __expf(pB[0]));
    ull A01 = pack2(__expf(pA[1]), __expf(pB[1]));
    ull A10 = pack2(__expf(pA[2]), __expf(pB[2]));
    ull A11 = pack2(__expf(pA[3]), __expf(pB[3]));
    const ull ONE = pack2(1.0f, 1.0f);
    ull A02 = ONE, A12 = ONE, A20 = ONE, A21 = ONE, A22 = ONE;

    float shm0A = 0.02f + 0.96f * frcp(1.0f + __expf(-pA[4]));
    float shm1A = 0.02f + 0.96f * frcp(1.0f + __expf(-pA[5]));
    float shf0A = 0.02f + 0.96f * frcp(1.0f + __expf(-pA[6]));
    float shf1A = 0.02f + 0.96f * frcp(1.0f + __expf(-pA[7]));
    float shm0B = 0.02f + 0.96f * frcp(1.0f + __expf(-pB[4]));
    float shm1B = 0.02f + 0.96f * frcp(1.0f + __expf(-pB[5]));
    float shf0B = 0.02f + 0.96f * frcp(1.0f + __expf(-pB[6]));
    float shf1B = 0.02f + 0.96f * frcp(1.0f + __expf(-pB[7]));
    float VA = __expf(pA[8]), VB = __expf(pB[8]);

    ull M0 = pack2(xA[0], xB[0]), M1 = pack2(xA[1], xB[1]), M2 = pack2(xA[2], xB[2]);
    ull F0 = pack2(xA[3], xB[3]), F1 = pack2(xA[4], xB[4]), F2 = pack2(xA[5], xB[5]);
    ull r0 = mul2(M0, pack2(shm0A, shm0B));
    ull r1 = mul2(M1, pack2(shm1A, shm1B));
    ull r2 = M2;
    ull c0 = mul2(F0, pack2(shf0A, shf0B));
    ull c1 = mul2(F1, pack2(shf1A, shf1B));
    ull c2 = F2;

    float um0A = xA[0] * (1.0f - shm0A), um1A = xA[1] * (1.0f - shm1A);
    float uf0A = xA[3] * (1.0f - shf0A), uf1A = xA[4] * (1.0f - shf1A);
    float um0B = xB[0] * (1.0f - shm0B), um1B = xB[1] * (1.0f - shm1B);
    float uf0B = xB[3] * (1.0f - shf0B), uf1B = xB[4] * (1.0f - shf1B);

    const ull EPS2 = pack2(EPSF, EPSF);

    #pragma unroll
    for (int it = 0; it < 10; it++) {
        // row normalize
        ull s0 = add2(add2(A00, A01), add2(A02, EPS2));
        ull s1 = add2(add2(A10, A11), add2(A12, EPS2));
        ull s2 = add2(add2(A20, A21), add2(A22, EPS2));
        float l, h;
        unpack2(s0, l, h); ull i0 = pack2(frcp(l), frcp(h));
        unpack2(s1, l, h); ull i1 = pack2(frcp(l), frcp(h));
        unpack2(s2, l, h); ull i2 = pack2(frcp(l), frcp(h));
        ull f0 = mul2(r0, i0), f1 = mul2(r1, i1), f2 = mul2(r2, i2);
        A00 = mul2(A00, f0); A01 = mul2(A01, f0); A02 = mul2(A02, f0);
        A10 = mul2(A10, f1); A11 = mul2(A11, f1); A12 = mul2(A12, f1);
        A20 = mul2(A20, f2); A21 = mul2(A21, f2); A22 = mul2(A22, f2);
        // column normalize
        ull t0 = add2(add2(A00, A10), add2(A20, EPS2));
        ull t1 = add2(add2(A01, A11), add2(A21, EPS2));
        ull t2 = add2(add2(A02, A12), add2(A22, EPS2));
        unpack2(t0, l, h); ull j0 = pack2(frcp(l), frcp(h));
        unpack2(t1, l, h); ull j1 = pack2(frcp(l), frcp(h));
        unpack2(t2, l, h); ull j2 = pack2(frcp(l), frcp(h));
        ull g0 = mul2(c0, j0), g1 = mul2(c1, j1), g2 = mul2(c2, j2);
        A00 = mul2(A00, g0); A10 = mul2(A10, g0); A20 = mul2(A20, g0);
        A01 = mul2(A01, g1); A11 = mul2(A11, g1); A21 = mul2(A21, g1);
        A02 = mul2(A02, g2); A12 = mul2(A12, g2); A22 = mul2(A22, g2);
    }

    float a00, a01, a02, a10, a11, a12, a20, a21, a22;
    float b00, b01, b02, b10, b11, b12, b20, b21, b22;
    unpack2(A00, a00, b00); unpack2(A01, a01, b01); unpack2(A02, a02, b02);
    unpack2(A10, a10, b10); unpack2(A11, a11, b11); unpack2(A12, a12, b12);
    unpack2(A20, a20, b20); unpack2(A21, a21, b21); unpack2(A22, a22, b22);

    float4* oA = reinterpret_cast<float4*>(out_mus + (size_t)rowA * 16);
    oA[0] = make_float4(a00, a01, a02, um0A);
    oA[1] = make_float4(a10, a11, a12, um1A);
    oA[2] = make_float4(a20, a21, a22, 0.0f);
    oA[3] = make_float4(uf0A, uf1A, 0.0f, 0.0f);
    out_V[rowA] = VA;

    float4* oB = reinterpret_cast<float4*>(out_mus + (size_t)rowB * 16);
    oB[0] = make_float4(b00, b01, b02, um0B);
    oB[1] = make_float4(b10, b11, b12, um1B);
    oB[2] = make_float4(b20, b21, b22, 0.0f);
    oB[3] = make_float4(uf0B, uf1B, 0.0f, 0.0f);
    out_V[rowB] = VB;
}

__global__ __launch_bounds__(THREADS)
void sinkhorn_unmatched_kernel(
    const float* __restrict__ margins,
    float* __restrict__ out_mus, float* __restrict__ out_V, int B)
{
    const int tid = threadIdx.x;
    int rowA = blockIdx.x * (2 * THREADS) + tid;
    int rowB = rowA + THREADS;
    if (rowB >= B) { if (rowA >= B) return; rowB = rowA; }

    const float2* m2 = reinterpret_cast<const float2*>(margins);
    float2 a0 = m2[rowA * 3 + 0], a1 = m2[rowA * 3 + 1], a2 = m2[rowA * 3 + 2];
    float2 b0 = m2[rowB * 3 + 0], b1v = m2[rowB * 3 + 1], b2v = m2[rowB * 3 + 2];
    float xA[6] = { a0.x, a0.y, a1.x, a1.y, a2.x, a2.y };
    float xB[6] = { b0.x, b0.y, b1v.x, b1v.y, b2v.x, b2v.y };

    // inputs packed over the two rows
    ull px[6];
    #pragma unroll
    for (int i = 0; i < 6; i++) px[i] = pack2(xA[i], xB[i]);

    // ---- fused L1 (6->64) + L2 (64->32) ----
    ull accA[16], accB[16];
    #pragma unroll
    for (int q = 0; q < 8; q++) {
        ulonglong2 t = cpar.b2p[q];
        accA[2 * q] = t.x; accA[2 * q + 1] = t.y;
        accB[2 * q] = t.x; accB[2 * q + 1] = t.y;
    }
    #pragma unroll 8
    for (int j = 0; j < 64; j++) {
        ulonglong2 w10 = cpar.W1p[j * 3 + 0];
        ulonglong2 w11 = cpar.W1p[j * 3 + 1];
        ulonglong2 w12 = cpar.W1p[j * 3 + 2];
        ull h = cpar.b1p[j];
        h = fma2(px[0], w10.x, h);
        h = fma2(px[1], w10.y, h);
        h = fma2(px[2], w11.x, h);
        h = fma2(px[3], w11.y, h);
        h = fma2(px[4], w12.x, h);
        h = fma2(px[5], w12.y, h);
        float ha, hb; unpack2(h, ha, hb);
        ha = fmaxf(ha, 0.0f); hb = fmaxf(hb, 0.0f);
        ull paa = pack2(ha, ha), pbb = pack2(hb, hb);
        #pragma unroll
        for (int q = 0; q < 8; q++) {
            ulonglong2 w = cpar.W2p[j * 8 + q];
            accA[2 * q]     = fma2(paa, w.x, accA[2 * q]);
            accA[2 * q + 1] = fma2(paa, w.y, accA[2 * q + 1]);
            accB[2 * q]     = fma2(pbb, w.x, accB[2 * q]);
            accB[2 * q + 1] = fma2(pbb, w.y, accB[2 * q + 1]);
        }
    }

    // ---- L3 (32->16) ----
    ull h3A[8], h3B[8];
    #pragma unroll
    for (int q = 0; q < 4; q++) {
        ulonglong2 t = cpar.b3p[q];
        h3A[2 * q] = t.x; h3A[2 * q + 1] = t.y;
        h3B[2 * q] = t.x; h3B[2 * q + 1] = t.y;
    }
    #pragma unroll 4
    for (int jp = 0; jp < 16; jp++) {
        float a0f, a1f, b0f, b1f;
        unpack2(accA[jp], a0f, a1f);
        unpack2(accB[jp], b0f, b1f);
        a0f = fmaxf(a0f, 0.0f); a1f = fmaxf(a1f, 0.0f);
        b0f = fmaxf(b0f, 0.0f); b1f = fmaxf(b1f, 0.0f);
        #pragma unroll
        for (int s = 0; s < 2; s++) {
            int j = 2 * jp + s;
            ull paa = pack2(s ? a1f : a0f, s ? a1f : a0f);
            ull pbb = pack2(s ? b1f : b0f, s ? b1f : b0f);
            #pragma unroll
            for (int q = 0; q < 4; q++) {
                ulonglong2 w = cpar.W3p[j * 4 + q];
                h3A[2 * q]     = fma2(paa, w.x, h3A[2 * q]);
                h3A[2 * q + 1] = fma2(paa, w.y, h3A[2 * q + 1]);
                h3B[2 * q]     = fma2(pbb, w.x, h3B[2 * q]);
                h3B[2 * q + 1] = fma2(pbb, w.y, h3B[2 * q + 1]);
            }
        }
    }

    // ---- L4 (16->9, padded 12) ----
    ull pAa[6], pBa[6];
    #pragma unroll
    for (int q = 0; q < 3; q++) {
        ulonglong2 t = cpar.b4p[q];
        pAa[2 * q] = t.x; pAa[2 * q + 1] = t.y;
        pBa[2 * q] = t.x; pBa[2 * q + 1] = t.y;
    }
    #pragma unroll 4
    for (int jp = 0; jp < 8; jp++) {
        float a0f, a1f, b0f, b1f;
        unpack2(h3A[jp], a0f, a1f);
        unpack2(h3B[jp], b0f, b1f);
        a0f = fmaxf(a0f, 0.0f); a1f = fmaxf(a1f, 0.0f);
        b0f = fmaxf(b0f, 0.0f); b1f = fmaxf(b1f, 0.0f);
        #pragma unroll
        for (int s = 0; s < 2; s++) {
            int j = 2 * jp + s;
            ull paa = pack2(s ? a1f : a0f, s ? a1f : a0f);
            ull pbb = pack2(s ? b1f : b0f, s ? b1f : b0f);
            #pragma unroll
            for (int q = 0; q < 3; q++) {
                ulonglong2 w = cpar.W4p[j * 3 + q];
                pAa[2 * q]     = fma2(paa, w.x, pAa[2 * q]);
                pAa[2 * q + 1] = fma2(paa, w.y, pAa[2 * q + 1]);
                pBa[2 * q]     = fma2(pbb, w.x, pBa[2 * q]);
                pBa[2 * q + 1] = fma2(pbb, w.y, pBa[2 * q + 1]);
            }
        }
    }

    float parsA[12], parsB[12];
    #pragma unroll
    for (int q = 0; q < 6; q++) {
        unpack2(pAa[q], parsA[2 * q], parsA[2 * q + 1]);
        unpack2(pBa[q], parsB[2 * q], parsB[2 * q + 1]);
    }

    head2(xA, xB, parsA, parsB, out_mus, out_V, rowA, rowB);
}

extern "C" void kernel_launch(void* const* d_in, const int* in_sizes, int n_in,
                              void* d_out, int out_size)
{
    const float* margins = (const float*)d_in[0];
    const float* W1 = (const float*)d_in[1];
    const float* b1 = (const float*)d_in[2];
    const float* W2 = (const float*)d_in[3];
    const float* b2 = (const float*)d_in[4];
    const float* W3 = (const float*)d_in[5];
    const float* b3 = (const float*)d_in[6];
    const float* W4 = (const float*)d_in[7];
    const float* b4 = (const float*)d_in[8];

    int B = in_sizes[0] / 6;
    float* out_mus = (float*)d_out;
    float* out_V = (float*)d_out + (size_t)B * 16;

    prep_kernel<<<1, 256>>>(W1, b1, W2, b2, W3, b3, W4, b4);

    void* cdst = nullptr; void* csrc = nullptr;
    cudaGetSymbolAddress(&cdst, cpar);
    cudaGetSymbolAddress(&csrc, g_stage);
    cudaMemcpyAsync(cdst, csrc, sizeof(CParams), cudaMemcpyDeviceToDevice, 0);

    int rows_per_block = 2 * THREADS;
    int blocks = (B + rows_per_block - 1) / rows_per_block;
    sinkhorn_unmatched_kernel<<<blocks, THREADS>>>(margins, out_mus, out_V, B);
}